// round 2
// baseline (speedup 1.0000x reference)
#include <cuda_runtime.h>
#include <cuda_bf16.h>
#include <cstdint>

#define BB   128
#define TT   1024
#define II   256
#define HH   256
#define G4   1024           // 4*H
#define NBLK 128            // persistent blocks in recurrent kernel

// ---------------- device scratch (static: no runtime allocation) ----------------
__device__ float g_xp[(size_t)TT * G4 * BB];   // [t][j][b]  512 MB
__device__ float g_y0[(size_t)TT * HH * BB];   // [t][u][b]  128 MB (layer0 out)
__device__ float g_y1[(size_t)TT * HH * BB];   // [t][u][b]  128 MB (layer1 out)
__device__ float g_h[2][HH * BB];              // ping-pong h, [k][b]
__device__ int   g_flags[NBLK];

// ---------------- fast activations: 1 MUFU each, rest on FMA pipe ----------------
__device__ __forceinline__ float fast_exp2(float x) {
    x = fminf(fmaxf(x, -126.0f), 126.0f);
    float r = rintf(x);
    float f = x - r;
    // 2^f on [-0.5, 0.5], |err| ~1e-8
    float p = 1.535336188319500e-4f;
    p = fmaf(p, f, 1.339887440266574e-3f);
    p = fmaf(p, f, 9.618437357674640e-3f);
    p = fmaf(p, f, 5.550332471162809e-2f);
    p = fmaf(p, f, 2.402264791363012e-1f);
    p = fmaf(p, f, 6.931472028550421e-1f);
    p = fmaf(p, f, 1.0f);
    return __int_as_float(__float_as_int(p) + ((int)r << 23));
}
__device__ __forceinline__ float fast_sigmoid(float x) {
    float e = fast_exp2(-1.4426950408889634f * x);
    return __fdividef(1.0f, 1.0f + e);
}
__device__ __forceinline__ float fast_tanh(float x) {
    float e = fast_exp2(-2.8853900817779268f * x);
    return __fdividef(2.0f, 1.0f + e) - 1.0f;
}

// ---------------- init: zero h ping-pong + flags ----------------
__global__ void init_kernel() {
    int i = blockIdx.x * 256 + threadIdx.x;       // 16384 threads
    float* h = (float*)g_h;
    for (int j = i; j < 2 * HH * BB; j += 16384) h[j] = 0.0f;
    if (i < NBLK) g_flags[i] = 0;
}

// ---------------- input-projection GEMM ----------------
// xp[t][j][b] = sum_k W[j,k] * A_t[k,b] + b_ih[j] + b_hh[j]
// MODE 0: A_t[k,b] = x[b, t, k]   (x: [B,T,I])
// MODE 1: A_t[k,b] = g_y0[t, k, b]
template<int MODE>
__global__ __launch_bounds__(256) void gemm_xp_kernel(
    const float* __restrict__ A,
    const float* __restrict__ W,          // layer slice [1024, 256]
    const float* __restrict__ bih,        // layer slice [1024]
    const float* __restrict__ bhh)        // layer slice [1024]
{
    const int t  = blockIdx.y;
    const int jt = blockIdx.x;            // 0..7
    __shared__ float sW[16][128];
    __shared__ float sA[16][132];         // stride 132 (16B-aligned, fewer conflicts)
    const int tid = threadIdx.x;
    const int tx = tid & 15, ty = tid >> 4;

    const float* Ap = (MODE == 0) ? A : (const float*)g_y0;

    float acc[8][8];
    #pragma unroll
    for (int i = 0; i < 8; i++)
        #pragma unroll
        for (int j = 0; j < 8; j++) acc[i][j] = 0.0f;

    for (int k0 = 0; k0 < 256; k0 += 16) {
        // W tile: 128 rows x 16 k (transpose into sW[k][row])
        {
            int l0 = tid * 2;
            #pragma unroll
            for (int q = 0; q < 2; q++) {
                int l = l0 + q;                 // 0..511
                int row = l >> 2;
                int kc  = (l & 3) * 4;
                float4 v = *(const float4*)&W[(size_t)(jt * 128 + row) * 256 + k0 + kc];
                sW[kc + 0][row] = v.x; sW[kc + 1][row] = v.y;
                sW[kc + 2][row] = v.z; sW[kc + 3][row] = v.w;
            }
        }
        if (MODE == 0) {
            int l0 = tid * 2;
            #pragma unroll
            for (int q = 0; q < 2; q++) {
                int l = l0 + q;
                int bb = l >> 2;
                int kc = (l & 3) * 4;
                float4 v = *(const float4*)&Ap[((size_t)bb * TT + t) * II + k0 + kc];
                sA[kc + 0][bb] = v.x; sA[kc + 1][bb] = v.y;
                sA[kc + 2][bb] = v.z; sA[kc + 3][bb] = v.w;
            }
        } else {
            int l0 = tid * 2;
            #pragma unroll
            for (int q = 0; q < 2; q++) {
                int l = l0 + q;
                int kk = l >> 5;                // 0..15
                int bc = (l & 31) * 4;          // 0..124
                float4 v = *(const float4*)&Ap[((size_t)t * HH + k0 + kk) * BB + bc];
                *(float4*)&sA[kk][bc] = v;
            }
        }
        __syncthreads();
        #pragma unroll
        for (int k = 0; k < 16; k++) {
            float wf[8], af[8];
            *(float4*)&wf[0] = *(const float4*)&sW[k][ty * 4];
            *(float4*)&wf[4] = *(const float4*)&sW[k][64 + ty * 4];
            *(float4*)&af[0] = *(const float4*)&sA[k][tx * 4];
            *(float4*)&af[4] = *(const float4*)&sA[k][64 + tx * 4];
            #pragma unroll
            for (int i = 0; i < 8; i++)
                #pragma unroll
                for (int j = 0; j < 8; j++)
                    acc[i][j] = fmaf(wf[i], af[j], acc[i][j]);
        }
        __syncthreads();
    }

    // epilogue: + (b_ih + b_hh), store xp[t][j][b]
    #pragma unroll
    for (int i = 0; i < 8; i++) {
        int jloc = (i < 4) ? (ty * 4 + i) : (64 + ty * 4 + (i - 4));
        int j = jt * 128 + jloc;
        float bsum = bih[j] + bhh[j];
        float4 o0 = make_float4(acc[i][0] + bsum, acc[i][1] + bsum,
                                acc[i][2] + bsum, acc[i][3] + bsum);
        float4 o1 = make_float4(acc[i][4] + bsum, acc[i][5] + bsum,
                                acc[i][6] + bsum, acc[i][7] + bsum);
        size_t base = ((size_t)t * G4 + j) * BB;
        *(float4*)&g_xp[base + tx * 4]      = o0;
        *(float4*)&g_xp[base + 64 + tx * 4] = o1;
    }
}

// ---------------- persistent recurrent kernel ----------------
// 128 blocks x 256 threads; block owns 2 hidden units x all 128 batches.
// Weights resident in SMEM; h staged into SMEM each step; single flag-barrier
// per step (ping-pong h removes the load/store race).
__global__ __launch_bounds__(256) void lstm_rec_kernel(
    const float* __restrict__ Whh,        // layer slice [1024, 256]
    const float* __restrict__ masks,      // layer slice [3,128,256]
    int layer)
{
    extern __shared__ float smem[];
    float4* sW = (float4*)smem;                 // [2][256] packed (wi,wf,wg,wo)
    float*  sH = smem + 2048;                   // [256][128]

    const int tid = threadIdx.x;
    const int b   = tid & 127;
    const int ul  = tid >> 7;                   // 0/1
    const int u   = blockIdx.x * 2 + ul;
    float* yout = (layer == 0) ? g_y0 : g_y1;

    // load W_hh rows for this block's 2 units, packed per k
    for (int idx = tid; idx < 512; idx += 256) {
        int uu = idx >> 8;
        int k  = idx & 255;
        int gu = blockIdx.x * 2 + uu;
        float wi = Whh[(size_t)(0 * HH + gu) * HH + k];
        float wf = Whh[(size_t)(1 * HH + gu) * HH + k];
        float wg = Whh[(size_t)(2 * HH + gu) * HH + k];
        float wo = Whh[(size_t)(3 * HH + gu) * HH + k];
        sW[idx] = make_float4(wi, wf, wg, wo);
    }
    const float om = masks[(size_t)(0 * BB + b) * HH + u];
    const float hm = masks[(size_t)(1 * BB + b) * HH + u];
    const float cm = masks[(size_t)(2 * BB + b) * HH + u];
    float c = 0.0f;
    __syncthreads();

    const float4* wrow = &sW[ul * 256];

    for (int t = 0; t < TT; t++) {
        // stage h(t) into SMEM (L2-coherent loads)
        const float4* hsrc = (const float4*)g_h[t & 1];
        #pragma unroll
        for (int i = tid; i < (HH * BB) / 4; i += 256)
            ((float4*)sH)[i] = __ldcg(&hsrc[i]);
        __syncthreads();

        size_t base = ((size_t)t * G4 + u) * BB + b;
        float ai = g_xp[base];
        float af = g_xp[base + 1 * HH * BB];
        float ag = g_xp[base + 2 * HH * BB];
        float ao = g_xp[base + 3 * HH * BB];

        #pragma unroll 8
        for (int k = 0; k < HH; k++) {
            float  hv = sH[k * BB + b];
            float4 w  = wrow[k];
            ai = fmaf(w.x, hv, ai);
            af = fmaf(w.y, hv, af);
            ag = fmaf(w.z, hv, ag);
            ao = fmaf(w.w, hv, ao);
        }

        float si = fast_sigmoid(ai);
        float sf = fast_sigmoid(af);
        float so = fast_sigmoid(ao);
        float tg = fast_tanh(ag);
        float c2 = fmaf(sf, c, si * tg);
        float h2 = so * fast_tanh(c2);
        c = c2 * cm;

        yout[((size_t)t * HH + u) * BB + b] = h2 * om;          // layer output
        __stcg(&g_h[(t + 1) & 1][u * BB + b], h2 * hm);         // carried h

        // ---- grid barrier: per-block flag + poll (no atomics) ----
        __threadfence();
        __syncthreads();
        if (tid == 0) ((volatile int*)g_flags)[blockIdx.x] = t + 1;
        if (tid < NBLK) {
            while (((volatile int*)g_flags)[tid] < t + 1) { }
            __threadfence();   // acquire
        }
        __syncthreads();
    }
}

// ---------------- final transpose: g_y1 [t][u][b] -> out [b][t][u] ----------------
__global__ void transpose_kernel(float* __restrict__ out) {
    __shared__ float tile[32][33];
    int t  = blockIdx.z;
    int u0 = blockIdx.x * 32;
    int b0 = blockIdx.y * 32;
    int x = threadIdx.x, y = threadIdx.y;     // 32 x 8
    #pragma unroll
    for (int i = 0; i < 32; i += 8)
        tile[y + i][x] = g_y1[((size_t)t * HH + u0 + y + i) * BB + b0 + x];
    __syncthreads();
    #pragma unroll
    for (int i = 0; i < 32; i += 8)
        out[((size_t)(b0 + y + i) * TT + t) * HH + u0 + x] = tile[x][y + i];
}

// ---------------- launch ----------------
extern "C" void kernel_launch(void* const* d_in, const int* in_sizes, int n_in,
                              void* d_out, int out_size) {
    const float* x     = (const float*)d_in[0];   // [128,1024,256]
    const float* W_ih  = (const float*)d_in[1];   // [2,1024,256]
    const float* W_hh  = (const float*)d_in[2];   // [2,1024,256]
    const float* b_ih  = (const float*)d_in[3];   // [2,1024]
    const float* b_hh  = (const float*)d_in[4];   // [2,1024]
    const float* masks = (const float*)d_in[5];   // [2,3,128,256]
    float* out = (float*)d_out;

    const int rec_smem = (2048 + HH * BB) * (int)sizeof(float);   // 139264 B
    cudaFuncSetAttribute(lstm_rec_kernel,
                         cudaFuncAttributeMaxDynamicSharedMemorySize, rec_smem);

    dim3 ggrid(8, TT);

    // ---- layer 0 ----
    init_kernel<<<64, 256>>>();
    gemm_xp_kernel<0><<<ggrid, 256>>>(x, W_ih, b_ih, b_hh);
    lstm_rec_kernel<<<NBLK, 256, rec_smem>>>(W_hh, masks, 0);

    // ---- layer 1 ----
    init_kernel<<<64, 256>>>();
    gemm_xp_kernel<1><<<ggrid, 256>>>(nullptr, W_ih + (size_t)G4 * II,
                                      b_ih + G4, b_hh + G4);
    lstm_rec_kernel<<<NBLK, 256, rec_smem>>>(W_hh + (size_t)G4 * HH,
                                             masks + (size_t)3 * BB * HH, 1);

    // ---- output transpose ----
    transpose_kernel<<<dim3(8, 4, TT), dim3(32, 8)>>>(out);
}

// round 3
// speedup vs baseline: 2.2683x; 2.2683x over previous
#include <cuda_runtime.h>
#include <cuda_bf16.h>
#include <cstdint>

#define BB   128
#define TT   1024
#define II   256
#define HH   256
#define G4   1024           // 4*H
#define NBLK 128            // persistent blocks in recurrent kernel

typedef unsigned long long ull;

// ---------------- device scratch (static: no runtime allocation) ----------------
__device__ float g_xp[(size_t)TT * G4 * BB];   // [t][j][b]
__device__ float g_y0[(size_t)TT * HH * BB];   // [t][u][b]  layer0 out
__device__ float g_y1[(size_t)TT * HH * BB];   // [t][u][b]  layer1 out
__device__ float g_h[2][HH * BB];              // ping-pong h, [k][b]
__device__ unsigned g_arrive;

// ---------------- f32x2 packed-FMA helpers (SASS FFMA2) ----------------
__device__ __forceinline__ void ffma2(ull &d, ull a, ull b) {
    asm("fma.rn.f32x2 %0, %1, %2, %0;" : "+l"(d) : "l"(a), "l"(b));
}
__device__ __forceinline__ ull dup2(float x) {
    ull r; asm("mov.b64 %0, {%1, %1};" : "=l"(r) : "f"(x)); return r;
}
__device__ __forceinline__ float2 unpack2(ull v) {
    float2 r; asm("mov.b64 {%0, %1}, %2;" : "=f"(r.x), "=f"(r.y) : "l"(v)); return r;
}

// ---------------- cp.async helpers ----------------
__device__ __forceinline__ void cp_async16(uint32_t saddr, const void* g) {
    asm volatile("cp.async.cg.shared.global [%0], [%1], 16;" :: "r"(saddr), "l"(g));
}
#define CP_COMMIT()  asm volatile("cp.async.commit_group;" ::: "memory")
#define CP_WAIT(n)   asm volatile("cp.async.wait_group %0;" :: "n"(n) : "memory")

// ---------------- fast activations: 1 MUFU each, rest on FMA pipe ----------------
__device__ __forceinline__ float fast_exp2(float x) {
    x = fminf(fmaxf(x, -126.0f), 126.0f);
    float r = rintf(x);
    float f = x - r;
    float p = 1.535336188319500e-4f;
    p = fmaf(p, f, 1.339887440266574e-3f);
    p = fmaf(p, f, 9.618437357674640e-3f);
    p = fmaf(p, f, 5.550332471162809e-2f);
    p = fmaf(p, f, 2.402264791363012e-1f);
    p = fmaf(p, f, 6.931472028550421e-1f);
    p = fmaf(p, f, 1.0f);
    return __int_as_float(__float_as_int(p) + ((int)r << 23));
}
__device__ __forceinline__ float fast_sigmoid(float x) {
    float e = fast_exp2(-1.4426950408889634f * x);
    return __fdividef(1.0f, 1.0f + e);
}
__device__ __forceinline__ float fast_tanh(float x) {
    float e = fast_exp2(-2.8853900817779268f * x);
    return __fdividef(2.0f, 1.0f + e) - 1.0f;
}

// ---------------- init: zero h ping-pong + arrival counter ----------------
__global__ void init_kernel() {
    int i = blockIdx.x * 256 + threadIdx.x;       // 16384 threads
    float* h = (float*)g_h;
    for (int j = i; j < 2 * HH * BB; j += 16384) h[j] = 0.0f;
    if (i == 0) g_arrive = 0u;
}

// ---------------- input-projection GEMM (FFMA2) ----------------
// xp[t][j][b] = sum_k W[j,k] * A_t[k,b] + b_ih[j] + b_hh[j]
// MODE 0: A_t[k,b] = x[b, t, k]   (x: [B,T,I])
// MODE 1: A_t[k,b] = g_y0[t, k, b]
template<int MODE>
__global__ __launch_bounds__(256) void gemm_xp_kernel(
    const float* __restrict__ A,
    const float* __restrict__ W,          // layer slice [1024, 256]
    const float* __restrict__ bih,
    const float* __restrict__ bhh)
{
    const int t  = blockIdx.y;
    const int jt = blockIdx.x;            // 0..7
    __shared__ __align__(16) float sW[16][128];
    __shared__ __align__(16) float sA[16][132];
    const int tid = threadIdx.x;
    const int tx = tid & 15, ty = tid >> 4;

    const float* Ap = (MODE == 0) ? A : (const float*)g_y0;

    ull acc[8][4];
    #pragma unroll
    for (int i = 0; i < 8; i++)
        #pragma unroll
        for (int j = 0; j < 4; j++) acc[i][j] = 0ULL;

    for (int k0 = 0; k0 < 256; k0 += 16) {
        {
            int l0 = tid * 2;
            #pragma unroll
            for (int q = 0; q < 2; q++) {
                int l = l0 + q;
                int row = l >> 2;
                int kc  = (l & 3) * 4;
                float4 v = *(const float4*)&W[(size_t)(jt * 128 + row) * 256 + k0 + kc];
                sW[kc + 0][row] = v.x; sW[kc + 1][row] = v.y;
                sW[kc + 2][row] = v.z; sW[kc + 3][row] = v.w;
            }
        }
        if (MODE == 0) {
            int l0 = tid * 2;
            #pragma unroll
            for (int q = 0; q < 2; q++) {
                int l = l0 + q;
                int bb = l >> 2;
                int kc = (l & 3) * 4;
                float4 v = *(const float4*)&Ap[((size_t)bb * TT + t) * II + k0 + kc];
                sA[kc + 0][bb] = v.x; sA[kc + 1][bb] = v.y;
                sA[kc + 2][bb] = v.z; sA[kc + 3][bb] = v.w;
            }
        } else {
            int l0 = tid * 2;
            #pragma unroll
            for (int q = 0; q < 2; q++) {
                int l = l0 + q;
                int kk = l >> 5;
                int bc = (l & 31) * 4;
                float4 v = *(const float4*)&Ap[((size_t)t * HH + k0 + kk) * BB + bc];
                *(float4*)&sA[kk][bc] = v;
            }
        }
        __syncthreads();
        #pragma unroll
        for (int k = 0; k < 16; k++) {
            float4 w0 = *(const float4*)&sW[k][ty * 4];
            float4 w1 = *(const float4*)&sW[k][64 + ty * 4];
            ulonglong2 a0 = *(const ulonglong2*)&sA[k][tx * 4];
            ulonglong2 a1 = *(const ulonglong2*)&sA[k][64 + tx * 4];
            ull av0 = a0.x, av1 = a0.y, av2 = a1.x, av3 = a1.y;
            float wf[8] = {w0.x, w0.y, w0.z, w0.w, w1.x, w1.y, w1.z, w1.w};
            #pragma unroll
            for (int i = 0; i < 8; i++) {
                ull wd = dup2(wf[i]);
                ffma2(acc[i][0], wd, av0);
                ffma2(acc[i][1], wd, av1);
                ffma2(acc[i][2], wd, av2);
                ffma2(acc[i][3], wd, av3);
            }
        }
        __syncthreads();
    }

    #pragma unroll
    for (int i = 0; i < 8; i++) {
        int jloc = (i < 4) ? (ty * 4 + i) : (64 + ty * 4 + (i - 4));
        int j = jt * 128 + jloc;
        float bsum = bih[j] + bhh[j];
        float2 p0 = unpack2(acc[i][0]);
        float2 p1 = unpack2(acc[i][1]);
        float2 p2 = unpack2(acc[i][2]);
        float2 p3 = unpack2(acc[i][3]);
        float4 o0 = make_float4(p0.x + bsum, p0.y + bsum, p1.x + bsum, p1.y + bsum);
        float4 o1 = make_float4(p2.x + bsum, p2.y + bsum, p3.x + bsum, p3.y + bsum);
        size_t base = ((size_t)t * G4 + j) * BB;
        *(float4*)&g_xp[base + tx * 4]      = o0;
        *(float4*)&g_xp[base + 64 + tx * 4] = o1;
    }
}

// ---------------- persistent recurrent kernel ----------------
// 128 blocks x 128 threads; thread owns batch b and BOTH of the block's units.
// FFMA2 gate-paired accumulators; cp.async 2-chunk h staging overlapping dot;
// release/acquire counter barrier (no CCTL.IVALL).
__global__ __launch_bounds__(128) void lstm_rec_kernel(
    const float* __restrict__ Whh,        // layer slice [1024, 256]
    const float* __restrict__ masks,      // layer slice [3,128,256]
    int layer)
{
    extern __shared__ float smem[];
    float4* sW4 = (float4*)smem;                // [2][256] packed (wi,wf,wg,wo)
    float*  sH  = smem + 2048;                  // [256][128]

    const int tid = threadIdx.x;                // 0..127 = b
    const int b   = tid;
    const int u0  = blockIdx.x * 2;
    const int u1  = u0 + 1;
    float* yout = (layer == 0) ? g_y0 : g_y1;

    // W_hh rows for the block's 2 units, packed per k
    for (int idx = tid; idx < 512; idx += 128) {
        int uu = idx >> 8;
        int k  = idx & 255;
        int gu = u0 + uu;
        float wi = Whh[(size_t)(0 * HH + gu) * HH + k];
        float wf = Whh[(size_t)(1 * HH + gu) * HH + k];
        float wg = Whh[(size_t)(2 * HH + gu) * HH + k];
        float wo = Whh[(size_t)(3 * HH + gu) * HH + k];
        sW4[idx] = make_float4(wi, wf, wg, wo);
    }
    const float om0 = masks[(size_t)(0 * BB + b) * HH + u0];
    const float om1 = masks[(size_t)(0 * BB + b) * HH + u1];
    const float hm0 = masks[(size_t)(1 * BB + b) * HH + u0];
    const float hm1 = masks[(size_t)(1 * BB + b) * HH + u1];
    const float cm0 = masks[(size_t)(2 * BB + b) * HH + u0];
    const float cm1 = masks[(size_t)(2 * BB + b) * HH + u1];
    float c0 = 0.0f, c1 = 0.0f;
    __syncthreads();

    const uint32_t sH_addr = (uint32_t)__cvta_generic_to_shared(sH);
    const ulonglong2* wv0p = (const ulonglong2*)sW4;          // unit 0: [256]
    const ulonglong2* wv1p = wv0p + 256;                      // unit 1

    for (int t = 0; t < TT; t++) {
        // ---- xp prefetch (DRAM, consumed ~2500 cyc later) ----
        size_t xb = (size_t)t * G4 * BB + b;
        float xi0 = __ldcs(&g_xp[xb + (size_t)(0 * HH + u0) * BB]);
        float xf0 = __ldcs(&g_xp[xb + (size_t)(1 * HH + u0) * BB]);
        float xg0 = __ldcs(&g_xp[xb + (size_t)(2 * HH + u0) * BB]);
        float xo0 = __ldcs(&g_xp[xb + (size_t)(3 * HH + u0) * BB]);
        float xi1 = __ldcs(&g_xp[xb + (size_t)(0 * HH + u1) * BB]);
        float xf1 = __ldcs(&g_xp[xb + (size_t)(1 * HH + u1) * BB]);
        float xg1 = __ldcs(&g_xp[xb + (size_t)(2 * HH + u1) * BB]);
        float xo1 = __ldcs(&g_xp[xb + (size_t)(3 * HH + u1) * BB]);

        // ---- stage h via cp.async, 2 chunks (k 0..127, 128..255) ----
        const float4* hsrc = (const float4*)g_h[t & 1];
        #pragma unroll
        for (int i = 0; i < 32; i++) {
            int idx = tid + i * 128;                  // 0..4095
            cp_async16(sH_addr + idx * 16, hsrc + idx);
        }
        CP_COMMIT();
        #pragma unroll
        for (int i = 0; i < 32; i++) {
            int idx = 4096 + tid + i * 128;           // 4096..8191
            cp_async16(sH_addr + idx * 16, hsrc + idx);
        }
        CP_COMMIT();

        ull aif0 = 0ULL, ago0 = 0ULL, aif1 = 0ULL, ago1 = 0ULL;

        CP_WAIT(1);
        __syncthreads();                               // chunk A ready
        #pragma unroll 8
        for (int k = 0; k < 128; k++) {
            float hv = sH[k * BB + b];
            ull h2 = dup2(hv);
            ulonglong2 w0 = wv0p[k];
            ulonglong2 w1 = wv1p[k];
            ffma2(aif0, w0.x, h2);
            ffma2(ago0, w0.y, h2);
            ffma2(aif1, w1.x, h2);
            ffma2(ago1, w1.y, h2);
        }
        CP_WAIT(0);
        __syncthreads();                               // chunk B ready
        #pragma unroll 8
        for (int k = 128; k < 256; k++) {
            float hv = sH[k * BB + b];
            ull h2 = dup2(hv);
            ulonglong2 w0 = wv0p[k];
            ulonglong2 w1 = wv1p[k];
            ffma2(aif0, w0.x, h2);
            ffma2(ago0, w0.y, h2);
            ffma2(aif1, w1.x, h2);
            ffma2(ago1, w1.y, h2);
        }

        float2 vif0 = unpack2(aif0), vgo0 = unpack2(ago0);
        float2 vif1 = unpack2(aif1), vgo1 = unpack2(ago1);
        float ai0 = vif0.x + xi0, af0 = vif0.y + xf0;
        float ag0 = vgo0.x + xg0, ao0 = vgo0.y + xo0;
        float ai1 = vif1.x + xi1, af1 = vif1.y + xf1;
        float ag1 = vgo1.x + xg1, ao1 = vgo1.y + xo1;

        float si0 = fast_sigmoid(ai0), sf0 = fast_sigmoid(af0);
        float so0 = fast_sigmoid(ao0), tg0 = fast_tanh(ag0);
        float si1 = fast_sigmoid(ai1), sf1 = fast_sigmoid(af1);
        float so1 = fast_sigmoid(ao1), tg1 = fast_tanh(ag1);
        float c20 = fmaf(sf0, c0, si0 * tg0);
        float c21 = fmaf(sf1, c1, si1 * tg1);
        float h20 = so0 * fast_tanh(c20);
        float h21 = so1 * fast_tanh(c21);
        c0 = c20 * cm0;
        c1 = c21 * cm1;

        yout[((size_t)t * HH + u0) * BB + b] = h20 * om0;
        yout[((size_t)t * HH + u1) * BB + b] = h21 * om1;
        __stcg(&g_h[(t + 1) & 1][u0 * BB + b], h20 * hm0);
        __stcg(&g_h[(t + 1) & 1][u1 * BB + b], h21 * hm1);

        // ---- grid barrier: release-add counter + single acquire poll ----
        __syncthreads();
        if (tid == 0) {
            asm volatile("red.release.gpu.global.add.u32 [%0], %1;"
                         :: "l"(&g_arrive), "r"(1u) : "memory");
            unsigned tgt = (unsigned)(t + 1) * NBLK;
            unsigned v;
            do {
                asm volatile("ld.acquire.gpu.global.u32 %0, [%1];"
                             : "=r"(v) : "l"(&g_arrive) : "memory");
            } while (v < tgt);
        }
        __syncthreads();
    }
}

// ---------------- final transpose: g_y1 [t][u][b] -> out [b][t][u] ----------------
__global__ void transpose_kernel(float* __restrict__ out) {
    __shared__ float tile[32][33];
    int t  = blockIdx.z;
    int u0 = blockIdx.x * 32;
    int b0 = blockIdx.y * 32;
    int x = threadIdx.x, y = threadIdx.y;     // 32 x 8
    #pragma unroll
    for (int i = 0; i < 32; i += 8)
        tile[y + i][x] = g_y1[((size_t)t * HH + u0 + y + i) * BB + b0 + x];
    __syncthreads();
    #pragma unroll
    for (int i = 0; i < 32; i += 8)
        out[((size_t)(b0 + y + i) * TT + t) * HH + u0 + x] = tile[x][y + i];
}

// ---------------- launch ----------------
extern "C" void kernel_launch(void* const* d_in, const int* in_sizes, int n_in,
                              void* d_out, int out_size) {
    const float* x     = (const float*)d_in[0];   // [128,1024,256]
    const float* W_ih  = (const float*)d_in[1];   // [2,1024,256]
    const float* W_hh  = (const float*)d_in[2];   // [2,1024,256]
    const float* b_ih  = (const float*)d_in[3];   // [2,1024]
    const float* b_hh  = (const float*)d_in[4];   // [2,1024]
    const float* masks = (const float*)d_in[5];   // [2,3,128,256]
    float* out = (float*)d_out;

    const int rec_smem = (2048 + HH * BB) * (int)sizeof(float);   // 139264 B
    cudaFuncSetAttribute(lstm_rec_kernel,
                         cudaFuncAttributeMaxDynamicSharedMemorySize, rec_smem);

    dim3 ggrid(8, TT);

    // ---- layer 0 ----
    init_kernel<<<64, 256>>>();
    gemm_xp_kernel<0><<<ggrid, 256>>>(x, W_ih, b_ih, b_hh);
    lstm_rec_kernel<<<NBLK, 128, rec_smem>>>(W_hh, masks, 0);

    // ---- layer 1 ----
    init_kernel<<<64, 256>>>();
    gemm_xp_kernel<1><<<ggrid, 256>>>(nullptr, W_ih + (size_t)G4 * II,
                                      b_ih + G4, b_hh + G4);
    lstm_rec_kernel<<<NBLK, 128, rec_smem>>>(W_hh + (size_t)G4 * HH,
                                             masks + (size_t)3 * BB * HH, 1);

    // ---- output transpose ----
    transpose_kernel<<<dim3(8, 4, TT), dim3(32, 8)>>>(out);
}

// round 7
// speedup vs baseline: 2.8294x; 1.2474x over previous
#include <cuda_runtime.h>
#include <cuda_bf16.h>
#include <cstdint>

#define BB   128
#define TT   1024
#define II   256
#define HH   256
#define G4   1024           // 4*H
#define NBLK 128

typedef unsigned long long ull;

// ---------------- device scratch ----------------
__device__ float g_xp[(size_t)TT * G4 * BB];   // [t][g][u][b]
__device__ float g_y0[(size_t)TT * HH * BB];   // [t][u][b]  layer0 out (GEMM-1 input)
__device__ float g_h[2][BB * HH];              // ping-pong h, [b][u]
__device__ unsigned g_arrive[8 * 32];          // 8 group counters, 128B apart

// ---------------- f32x2 packed-FMA helpers ----------------
__device__ __forceinline__ void ffma2(ull &d, ull a, ull b) {
    asm("fma.rn.f32x2 %0, %1, %2, %0;" : "+l"(d) : "l"(a), "l"(b));
}
__device__ __forceinline__ ull dup2(float x) {
    ull r; asm("mov.b64 %0, {%1, %1};" : "=l"(r) : "f"(x)); return r;
}
__device__ __forceinline__ float2 unpack2(ull v) {
    float2 r; asm("mov.b64 {%0, %1}, %2;" : "=f"(r.x), "=f"(r.y) : "l"(v)); return r;
}

// ---------------- cp.async helpers ----------------
__device__ __forceinline__ void cp_async16(uint32_t saddr, const void* g) {
    asm volatile("cp.async.cg.shared.global [%0], [%1], 16;" :: "r"(saddr), "l"(g));
}
#define CP_COMMIT()  asm volatile("cp.async.commit_group;" ::: "memory")
#define CP_WAIT(n)   asm volatile("cp.async.wait_group %0;" :: "n"(n) : "memory")

// ---------------- fast activations ----------------
__device__ __forceinline__ float fast_exp2(float x) {
    x = fminf(fmaxf(x, -126.0f), 126.0f);
    float r = rintf(x);
    float f = x - r;
    float p = 1.535336188319500e-4f;
    p = fmaf(p, f, 1.339887440266574e-3f);
    p = fmaf(p, f, 9.618437357674640e-3f);
    p = fmaf(p, f, 5.550332471162809e-2f);
    p = fmaf(p, f, 2.402264791363012e-1f);
    p = fmaf(p, f, 6.931472028550421e-1f);
    p = fmaf(p, f, 1.0f);
    return __int_as_float(__float_as_int(p) + ((int)r << 23));
}
__device__ __forceinline__ float fast_sigmoid(float x) {
    float e = fast_exp2(-1.4426950408889634f * x);
    return __fdividef(1.0f, 1.0f + e);
}
__device__ __forceinline__ float fast_tanh(float x) {
    float e = fast_exp2(-2.8853900817779268f * x);
    return __fdividef(2.0f, 1.0f + e) - 1.0f;
}

// ---------------- init ----------------
__global__ void init_kernel() {
    int i = blockIdx.x * 256 + threadIdx.x;       // 16384 threads
    float* h = (float*)g_h;
    for (int j = i; j < 2 * HH * BB; j += 16384) h[j] = 0.0f;
    if (i < 8 * 32) g_arrive[i] = 0u;
}

// ---------------- input-projection GEMM ----------------
// xp[t][j][b] = sum_k W[j,k] * A_t[k,b] + b_ih[j] + b_hh[j]   (j = g*256+u)
template<int MODE>
__global__ __launch_bounds__(256) void gemm_xp_kernel(
    const float* __restrict__ A,
    const float* __restrict__ W,
    const float* __restrict__ bih,
    const float* __restrict__ bhh)
{
    const int t  = blockIdx.y;
    const int jt = blockIdx.x;            // 0..7
    __shared__ __align__(16) float sW[16][128];
    __shared__ __align__(16) float sA[16][132];
    const int tid = threadIdx.x;
    const int tx = tid & 15, ty = tid >> 4;

    const float* Ap = (MODE == 0) ? A : (const float*)g_y0;

    ull acc[8][4];
    #pragma unroll
    for (int i = 0; i < 8; i++)
        #pragma unroll
        for (int j = 0; j < 4; j++) acc[i][j] = 0ULL;

    for (int k0 = 0; k0 < 256; k0 += 16) {
        {
            int l0 = tid * 2;
            #pragma unroll
            for (int q = 0; q < 2; q++) {
                int l = l0 + q;
                int row = l >> 2;
                int kc  = (l & 3) * 4;
                float4 v = *(const float4*)&W[(size_t)(jt * 128 + row) * 256 + k0 + kc];
                sW[kc + 0][row] = v.x; sW[kc + 1][row] = v.y;
                sW[kc + 2][row] = v.z; sW[kc + 3][row] = v.w;
            }
        }
        if (MODE == 0) {
            int l0 = tid * 2;
            #pragma unroll
            for (int q = 0; q < 2; q++) {
                int l = l0 + q;
                int bb = l >> 2;
                int kc = (l & 3) * 4;
                float4 v = *(const float4*)&Ap[((size_t)bb * TT + t) * II + k0 + kc];
                sA[kc + 0][bb] = v.x; sA[kc + 1][bb] = v.y;
                sA[kc + 2][bb] = v.z; sA[kc + 3][bb] = v.w;
            }
        } else {
            int l0 = tid * 2;
            #pragma unroll
            for (int q = 0; q < 2; q++) {
                int l = l0 + q;
                int kk = l >> 5;
                int bc = (l & 31) * 4;
                float4 v = *(const float4*)&Ap[((size_t)t * HH + k0 + kk) * BB + bc];
                *(float4*)&sA[kk][bc] = v;
            }
        }
        __syncthreads();
        #pragma unroll
        for (int k = 0; k < 16; k++) {
            float4 w0 = *(const float4*)&sW[k][ty * 4];
            float4 w1 = *(const float4*)&sW[k][64 + ty * 4];
            ulonglong2 a0 = *(const ulonglong2*)&sA[k][tx * 4];
            ulonglong2 a1 = *(const ulonglong2*)&sA[k][64 + tx * 4];
            ull av0 = a0.x, av1 = a0.y, av2 = a1.x, av3 = a1.y;
            float wf[8] = {w0.x, w0.y, w0.z, w0.w, w1.x, w1.y, w1.z, w1.w};
            #pragma unroll
            for (int i = 0; i < 8; i++) {
                ull wd = dup2(wf[i]);
                ffma2(acc[i][0], wd, av0);
                ffma2(acc[i][1], wd, av1);
                ffma2(acc[i][2], wd, av2);
                ffma2(acc[i][3], wd, av3);
            }
        }
        __syncthreads();
    }

    #pragma unroll
    for (int i = 0; i < 8; i++) {
        int jloc = (i < 4) ? (ty * 4 + i) : (64 + ty * 4 + (i - 4));
        int j = jt * 128 + jloc;
        float bsum = bih[j] + bhh[j];
        float2 p0 = unpack2(acc[i][0]);
        float2 p1 = unpack2(acc[i][1]);
        float2 p2 = unpack2(acc[i][2]);
        float2 p3 = unpack2(acc[i][3]);
        float4 o0 = make_float4(p0.x + bsum, p0.y + bsum, p1.x + bsum, p1.y + bsum);
        float4 o1 = make_float4(p2.x + bsum, p2.y + bsum, p3.x + bsum, p3.y + bsum);
        size_t base = ((size_t)t * G4 + j) * BB;
        *(float4*)&g_xp[base + tx * 4]      = o0;
        *(float4*)&g_xp[base + 64 + tx * 4] = o1;
    }
}

// ---------------- persistent recurrent kernel: 2D tiles ----------------
// grid 128 = 8 bt-groups x 16 ut.  Block owns 16 units x 16 batches.
// Thread (u_l, b_l): tid = u_l*16 + b_l.  FFMA2 2-way dot over k pairs.
// h stored [b][u]; each block stages only its 16 rows (16KB).
// Barrier is per-bt-group (16 blocks).
// LAYER 0 writes g_y0 (device symbol resolved IN DEVICE CODE — a __device__
// array must never be passed as a kernel argument from host code).
#define SW_U   1044           // per-u float stride in sW (4 gates x 260 + 4)
#define SW_G   260
#define SH_ROW 260            // per-b float stride in sH
#define SO_ROW 20             // staging row stride

template<int LAYER>
__global__ __launch_bounds__(256) void lstm_rec_kernel(
    const float* __restrict__ Whh,        // layer slice [4*256, 256]
    const float* __restrict__ masks,      // layer slice [3,128,256]
    float* __restrict__ out1)             // only used for LAYER==1: out [b][t][u]
{
    extern __shared__ float smem[];
    float* sW   = smem;                        // 16 * 1044
    float* sH   = smem + 16 * SW_U;            // 16 * 260
    float* sOut = sH + 16 * SH_ROW;            // 16 * 20
    float* sHn  = sOut + 16 * SO_ROW;          // 16 * 20

    const int tid = threadIdx.x;
    const int u_l = tid >> 4;                  // 0..15
    const int b_l = tid & 15;                  // 0..15
    const int bt  = blockIdx.x >> 4;           // 0..7  (barrier group)
    const int ut  = blockIdx.x & 15;           // 0..15
    const int u_g = ut * 16 + u_l;
    const int b_g = bt * 16 + b_l;

    float* yout = (LAYER == 0) ? g_y0 : out1;  // device-side symbol resolution

    // ---- load W_hh tile: [u_l][gate][k], padded ----
    for (int i = tid; i < 16 * 4 * 256; i += 256) {
        int uu = i >> 10;
        int g  = (i >> 8) & 3;
        int k  = i & 255;
        sW[uu * SW_U + g * SW_G + k] = Whh[(size_t)(g * HH + ut * 16 + uu) * HH + k];
    }
    const float om = masks[(size_t)(0 * BB + b_g) * HH + u_g];
    const float hm = masks[(size_t)(1 * BB + b_g) * HH + u_g];
    const float cm = masks[(size_t)(2 * BB + b_g) * HH + u_g];
    float c = 0.0f;
    __syncthreads();

    const uint32_t sH_base = (uint32_t)__cvta_generic_to_shared(sH);
    const float* wrow = &sW[u_l * SW_U];
    volatile unsigned* ctr = &g_arrive[bt * 32];

    // cp.async assignment: 8 threads per row, each owns 16 floats (4x16B)
    const int cp_row = (tid & 127) >> 3;       // 0..15
    const int cp_ch  = (tid & 7);              // 0..7  -> floats cp_ch*16 .. +15

    for (int t = 0; t < TT; t++) {
        // ---- xp prefetch: 4 gates, coalesced 64B runs per (g,u) ----
        size_t xb = (size_t)t * (size_t)G4 * BB + b_g;
        float xi = __ldcs(&g_xp[xb + (size_t)(0 * HH + u_g) * BB]);
        float xf = __ldcs(&g_xp[xb + (size_t)(1 * HH + u_g) * BB]);
        float xg = __ldcs(&g_xp[xb + (size_t)(2 * HH + u_g) * BB]);
        float xo = __ldcs(&g_xp[xb + (size_t)(3 * HH + u_g) * BB]);

        // ---- stage h rows [b_g][0..255] in two k-halves ----
        const float* hsrc = g_h[t & 1];
        if (tid < 128) {
            int fo = cp_ch * 16;                          // float offset in k-half 0
            #pragma unroll
            for (int q = 0; q < 4; q++)
                cp_async16(sH_base + (cp_row * SH_ROW + fo + q * 4) * 4,
                           &hsrc[(size_t)(bt * 16 + cp_row) * HH + fo + q * 4]);
        }
        CP_COMMIT();
        if (tid >= 128) {
            int fo = 128 + cp_ch * 16;                    // float offset in k-half 1
            #pragma unroll
            for (int q = 0; q < 4; q++)
                cp_async16(sH_base + (cp_row * SH_ROW + fo + q * 4) * 4,
                           &hsrc[(size_t)(bt * 16 + cp_row) * HH + fo + q * 4]);
        }
        CP_COMMIT();

        ull ai2 = 0ULL, af2 = 0ULL, ag2 = 0ULL, ao2 = 0ULL;

        CP_WAIT(1);
        __syncthreads();                       // first k-half ready
        #pragma unroll 8
        for (int k = 0; k < 128; k += 4) {
            ulonglong2 h4 = *(const ulonglong2*)&sH[b_l * SH_ROW + k];
            ulonglong2 wi = *(const ulonglong2*)&wrow[0 * SW_G + k];
            ulonglong2 wf = *(const ulonglong2*)&wrow[1 * SW_G + k];
            ulonglong2 wg = *(const ulonglong2*)&wrow[2 * SW_G + k];
            ulonglong2 wo = *(const ulonglong2*)&wrow[3 * SW_G + k];
            ffma2(ai2, wi.x, h4.x); ffma2(ai2, wi.y, h4.y);
            ffma2(af2, wf.x, h4.x); ffma2(af2, wf.y, h4.y);
            ffma2(ag2, wg.x, h4.x); ffma2(ag2, wg.y, h4.y);
            ffma2(ao2, wo.x, h4.x); ffma2(ao2, wo.y, h4.y);
        }
        CP_WAIT(0);
        __syncthreads();                       // second k-half ready
        #pragma unroll 8
        for (int k = 128; k < 256; k += 4) {
            ulonglong2 h4 = *(const ulonglong2*)&sH[b_l * SH_ROW + k];
            ulonglong2 wi = *(const ulonglong2*)&wrow[0 * SW_G + k];
            ulonglong2 wf = *(const ulonglong2*)&wrow[1 * SW_G + k];
            ulonglong2 wg = *(const ulonglong2*)&wrow[2 * SW_G + k];
            ulonglong2 wo = *(const ulonglong2*)&wrow[3 * SW_G + k];
            ffma2(ai2, wi.x, h4.x); ffma2(ai2, wi.y, h4.y);
            ffma2(af2, wf.x, h4.x); ffma2(af2, wf.y, h4.y);
            ffma2(ag2, wg.x, h4.x); ffma2(ag2, wg.y, h4.y);
            ffma2(ao2, wo.x, h4.x); ffma2(ao2, wo.y, h4.y);
        }

        float2 pi = unpack2(ai2), pf = unpack2(af2);
        float2 pg = unpack2(ag2), po = unpack2(ao2);
        float ai = pi.x + pi.y + xi;
        float af = pf.x + pf.y + xf;
        float ag = pg.x + pg.y + xg;
        float ao = po.x + po.y + xo;

        float si = fast_sigmoid(ai);
        float sf = fast_sigmoid(af);
        float so = fast_sigmoid(ao);
        float tg = fast_tanh(ag);
        float c2 = fmaf(sf, c, si * tg);
        float h2 = so * fast_tanh(c2);
        c = c2 * cm;

        // ---- stage outputs for coalesced writes ----
        if (LAYER == 0) sOut[u_l * SO_ROW + b_l] = h2 * om;   // y0[t][u][b]
        else            sOut[b_l * SO_ROW + u_l] = h2 * om;   // out[b][t][u]
        sHn[b_l * SO_ROW + u_l] = h2 * hm;                    // g_h[b][u]
        __syncthreads();

        if (tid < 64) {                        // y / out
            int r = tid >> 2, cc = tid & 3;
            float4 v = *(const float4*)&sOut[r * SO_ROW + cc * 4];
            if (LAYER == 0)
                *(float4*)&yout[((size_t)t * HH + ut * 16 + r) * BB + bt * 16 + cc * 4] = v;
            else
                *(float4*)&yout[((size_t)(bt * 16 + r) * TT + t) * HH + ut * 16 + cc * 4] = v;
        } else if (tid < 128) {                // next h
            int w = tid - 64;
            int r = w >> 2, cc = w & 3;
            float4 v = *(const float4*)&sHn[r * SO_ROW + cc * 4];
            *(float4*)&g_h[(t + 1) & 1][(size_t)(bt * 16 + r) * HH + ut * 16 + cc * 4] = v;
        }

        // ---- per-group barrier (16 blocks sharing bt) ----
        __syncthreads();
        if (tid == 0) {
            asm volatile("red.release.gpu.global.add.u32 [%0], %1;"
                         :: "l"((unsigned*)ctr), "r"(1u) : "memory");
            unsigned tgt = (unsigned)(t + 1) * 16u;
            unsigned v;
            do {
                asm volatile("ld.acquire.gpu.global.u32 %0, [%1];"
                             : "=r"(v) : "l"((unsigned*)ctr) : "memory");
            } while (v < tgt);
        }
        __syncthreads();
    }
}

// ---------------- launch ----------------
extern "C" void kernel_launch(void* const* d_in, const int* in_sizes, int n_in,
                              void* d_out, int out_size) {
    const float* x     = (const float*)d_in[0];   // [128,1024,256]
    const float* W_ih  = (const float*)d_in[1];   // [2,1024,256]
    const float* W_hh  = (const float*)d_in[2];   // [2,1024,256]
    const float* b_ih  = (const float*)d_in[3];   // [2,1024]
    const float* b_hh  = (const float*)d_in[4];   // [2,1024]
    const float* masks = (const float*)d_in[5];   // [2,3,128,256]
    float* out = (float*)d_out;

    const int rec_smem = (16 * SW_U + 16 * SH_ROW + 32 * SO_ROW) * (int)sizeof(float);
    cudaFuncSetAttribute(lstm_rec_kernel<0>,
                         cudaFuncAttributeMaxDynamicSharedMemorySize, rec_smem);
    cudaFuncSetAttribute(lstm_rec_kernel<1>,
                         cudaFuncAttributeMaxDynamicSharedMemorySize, rec_smem);

    dim3 ggrid(8, TT);

    // ---- layer 0 ----
    init_kernel<<<64, 256>>>();
    gemm_xp_kernel<0><<<ggrid, 256>>>(x, W_ih, b_ih, b_hh);
    lstm_rec_kernel<0><<<NBLK, 256, rec_smem>>>(W_hh, masks, nullptr);

    // ---- layer 1 ----
    init_kernel<<<64, 256>>>();
    gemm_xp_kernel<1><<<ggrid, 256>>>(nullptr, W_ih + (size_t)G4 * II,
                                      b_ih + G4, b_hh + G4);
    lstm_rec_kernel<1><<<NBLK, 256, rec_smem>>>(W_hh + (size_t)G4 * HH,
                                                masks + (size_t)3 * BB * HH, out);
}